// round 4
// baseline (speedup 1.0000x reference)
#include <cuda_runtime.h>
#include <math.h>

// Problem constants (shapes fixed by the dataset)
#define MSAMP 16384

// ---------------- scratch (device globals; no runtime allocation) ----------------
__device__ float g_H1p[MSAMP * 512];          // pos layer-1 activations (sigmoid)
__device__ float g_H2p[MSAMP * 512];          // pos layer-2 activations
__device__ float g_Ap [MSAMP * 3 * 512];      // pos backward seeds  sigma2' * W2[:,o]
__device__ float g_G1p[MSAMP * 3 * 512];      // pos backward layer-1 grads (incl sigma1')
__device__ float g_H1r[3 * MSAMP * 256];      // heads layer-1 activations
__device__ float g_H2r[3 * MSAMP * 256];      // heads layer-2 activations
__device__ float g_Ar [3 * MSAMP * 2 * 256];  // heads backward seeds
__device__ float g_G1r[3 * MSAMP * 2 * 256];  // heads backward grads (incl sigma1')
__device__ float g_W1pT[512 * 512];           // W1 pos transposed
__device__ float g_W1rT[3 * 256 * 256];       // W1 heads transposed
__device__ float g_aux[MSAMP * 9];            // per-sample: P0..2, (y0,y1) per head

__device__ __forceinline__ float sigf(float z) { return 1.0f / (1.0f + expf(-z)); }

__device__ __forceinline__ float wred(float v) {
#pragma unroll
    for (int o = 16; o; o >>= 1) v += __shfl_xor_sync(0xffffffffu, v, o);
    return v;
}

// ---------------- square matrix transpose (n multiple of 32) ----------------
__global__ void transpose_kernel(const float* __restrict__ in, float* __restrict__ out, int n) {
    __shared__ float tile[32][33];
    int bx = blockIdx.x * 32, by = blockIdx.y * 32;
    int tx = threadIdx.x, ty = threadIdx.y;
#pragma unroll
    for (int r = 0; r < 32; r += 8)
        tile[ty + r][tx] = in[(size_t)(by + ty + r) * n + bx + tx];
    __syncthreads();
#pragma unroll
    for (int r = 0; r < 32; r += 8)
        out[(size_t)(bx + ty + r) * n + by + tx] = tile[tx][ty + r];
}

// ---------------- layer 1 forward: H1 = sigmoid(q @ W0 + b0), K=7 ----------------
__global__ void fwd1_kernel(const float* __restrict__ x, const float* __restrict__ W0,
                            const float* __restrict__ b0, float* __restrict__ H1, int width) {
    int n = blockIdx.x * 256 + threadIdx.x;
    int s = blockIdx.y;
    const float* q = x + (size_t)s * 14;
    float z = b0[n];
#pragma unroll
    for (int j = 0; j < 7; ++j) z += q[j] * W0[j * width + n];
    H1[(size_t)s * width + n] = sigf(z);
}

// ---------------- tiled SGEMM: C = epi(A @ B) ----------------
// A: Mrows x K (lda=K), B: K x N row-major (ldb=N), C: Mrows x N.
// BM=128, BN=64, BK=16, 256 threads, 8x4 per thread, double-buffered smem.
// EPI==1: C = sigmoid(acc + bias[n])
// EPI==2: C = acc * h*(1-h)  with h = Hs[(row/O)*N + n]
template <int EPI>
__global__ __launch_bounds__(256) void sgemm_kernel(
    int K, int N,
    const float* __restrict__ A, const float* __restrict__ B,
    const float* __restrict__ bias, const float* __restrict__ Hs, int O,
    float* __restrict__ C) {
    __shared__ float As[2][16][128];
    __shared__ float Bs[2][16][64];

    const int tid = threadIdx.x;
    const int tx = tid & 15;
    const int ty = tid >> 4;

    const float* Ab = A + (size_t)blockIdx.y * 128 * K;
    const float* Bb = B + (size_t)blockIdx.x * 64;

    const int arow = tid >> 2;            // 0..63 (second vec: +64)
    const int akv  = (tid & 3) << 2;      // 0,4,8,12
    const int brow = tid >> 4;            // 0..15
    const int bn   = (tid & 15) << 2;     // 0..60

    float4 pa0, pa1, pb;
    // prologue: tile 0
    pa0 = *(const float4*)(Ab + (size_t)arow * K + akv);
    pa1 = *(const float4*)(Ab + (size_t)(arow + 64) * K + akv);
    pb  = *(const float4*)(Bb + (size_t)brow * N + bn);
    As[0][akv + 0][arow] = pa0.x; As[0][akv + 1][arow] = pa0.y;
    As[0][akv + 2][arow] = pa0.z; As[0][akv + 3][arow] = pa0.w;
    As[0][akv + 0][arow + 64] = pa1.x; As[0][akv + 1][arow + 64] = pa1.y;
    As[0][akv + 2][arow + 64] = pa1.z; As[0][akv + 3][arow + 64] = pa1.w;
    *(float4*)&Bs[0][brow][bn] = pb;
    __syncthreads();

    float acc[8][4];
#pragma unroll
    for (int i = 0; i < 8; ++i)
#pragma unroll
        for (int j = 0; j < 4; ++j) acc[i][j] = 0.0f;

    const int NT = K >> 4;
    for (int kt = 0; kt < NT; ++kt) {
        const int cur = kt & 1;
        if (kt + 1 < NT) {
            const int k0 = (kt + 1) << 4;
            pa0 = *(const float4*)(Ab + (size_t)arow * K + k0 + akv);
            pa1 = *(const float4*)(Ab + (size_t)(arow + 64) * K + k0 + akv);
            pb  = *(const float4*)(Bb + (size_t)(k0 + brow) * N + bn);
        }
#pragma unroll
        for (int k = 0; k < 16; ++k) {
            float a[8], b[4];
            *(float4*)(a + 0) = *(const float4*)&As[cur][k][ty * 8];
            *(float4*)(a + 4) = *(const float4*)&As[cur][k][ty * 8 + 4];
            *(float4*)(b + 0) = *(const float4*)&Bs[cur][k][tx * 4];
#pragma unroll
            for (int i = 0; i < 8; ++i)
#pragma unroll
                for (int j = 0; j < 4; ++j) acc[i][j] += a[i] * b[j];
        }
        if (kt + 1 < NT) {
            const int nb = cur ^ 1;
            As[nb][akv + 0][arow] = pa0.x; As[nb][akv + 1][arow] = pa0.y;
            As[nb][akv + 2][arow] = pa0.z; As[nb][akv + 3][arow] = pa0.w;
            As[nb][akv + 0][arow + 64] = pa1.x; As[nb][akv + 1][arow + 64] = pa1.y;
            As[nb][akv + 2][arow + 64] = pa1.z; As[nb][akv + 3][arow + 64] = pa1.w;
            *(float4*)&Bs[nb][brow][bn] = pb;
        }
        __syncthreads();
    }

    const int row0 = blockIdx.y * 128 + ty * 8;
    const int col0 = blockIdx.x * 64 + tx * 4;
    if (EPI == 1) {
        float4 bb = *(const float4*)(bias + col0);
#pragma unroll
        for (int i = 0; i < 8; ++i) {
            float4 v;
            v.x = sigf(acc[i][0] + bb.x);
            v.y = sigf(acc[i][1] + bb.y);
            v.z = sigf(acc[i][2] + bb.z);
            v.w = sigf(acc[i][3] + bb.w);
            *(float4*)(C + (size_t)(row0 + i) * N + col0) = v;
        }
    } else {
#pragma unroll
        for (int i = 0; i < 8; ++i) {
            int srow = (row0 + i) / O;
            float4 h = *(const float4*)(Hs + (size_t)srow * N + col0);
            float4 v;
            v.x = acc[i][0] * h.x * (1.0f - h.x);
            v.y = acc[i][1] * h.y * (1.0f - h.y);
            v.z = acc[i][2] * h.z * (1.0f - h.z);
            v.w = acc[i][3] * h.w * (1.0f - h.w);
            *(float4*)(C + (size_t)(row0 + i) * N + col0) = v;
        }
    }
}

// ---------------- seed kernel: output-layer dots + backward seeds ----------------
// warp per sample. pos: P = H2@W2+b2, Ap[s,o,i] = h(1-h)*W2[i,o].
// heads: y0,y1 and Ar[s,o,i].
__global__ __launch_bounds__(128) void seed_kernel(
    const float* __restrict__ W2p, const float* __restrict__ b2p,
    const float* __restrict__ W2r0, const float* __restrict__ b2r0,
    const float* __restrict__ W2r1, const float* __restrict__ b2r1,
    const float* __restrict__ W2r2, const float* __restrict__ b2r2,
    int m) {
    const int lane = threadIdx.x & 31;
    const int s = blockIdx.x * 4 + (threadIdx.x >> 5);

    {
        const float* h2 = g_H2p + (size_t)s * 512;
        float* ap = g_Ap + (size_t)s * 1536;
        float a0 = 0.f, a1 = 0.f, a2 = 0.f;
        for (int i = lane; i < 512; i += 32) {
            float h = h2[i], d = h * (1.0f - h);
            float w0 = W2p[i * 3 + 0], w1 = W2p[i * 3 + 1], w2 = W2p[i * 3 + 2];
            a0 += h * w0; a1 += h * w1; a2 += h * w2;
            ap[i] = d * w0; ap[512 + i] = d * w1; ap[1024 + i] = d * w2;
        }
        a0 = wred(a0); a1 = wred(a1); a2 = wred(a2);
        if (lane == 0) {
            g_aux[s * 9 + 0] = a0 + b2p[0];
            g_aux[s * 9 + 1] = a1 + b2p[1];
            g_aux[s * 9 + 2] = a2 + b2p[2];
        }
    }
    const float* W2h[3] = {W2r0, W2r1, W2r2};
    const float* b2h[3] = {b2r0, b2r1, b2r2};
#pragma unroll
    for (int t = 0; t < 3; ++t) {
        const float* h2 = g_H2r + ((size_t)t * m + s) * 256;
        float* ar = g_Ar + ((size_t)t * m + s) * 512;
        const float* W = W2h[t];
        float a0 = 0.f, a1 = 0.f;
        for (int i = lane; i < 256; i += 32) {
            float h = h2[i], d = h * (1.0f - h);
            float w0 = W[i * 2 + 0], w1 = W[i * 2 + 1];
            a0 += h * w0; a1 += h * w1;
            ar[i] = d * w0; ar[256 + i] = d * w1;
        }
        a0 = wred(a0); a1 = wred(a1);
        if (lane == 0) {
            g_aux[s * 9 + 3 + 2 * t] = a0 + b2h[t][0];
            g_aux[s * 9 + 4 + 2 * t] = a1 + b2h[t][1];
        }
    }
}

// ---------------- final kernel: J projection to inputs, chain rule, assembly ----------------
__global__ __launch_bounds__(128) void final_kernel(
    const float* __restrict__ x,
    const float* __restrict__ W0p,
    const float* __restrict__ W0r0, const float* __restrict__ W0r1, const float* __restrict__ W0r2,
    float* __restrict__ out, int m) {
    __shared__ float sWp[7 * 512];
    __shared__ float sWr[3][7 * 256];
    for (int i = threadIdx.x; i < 7 * 512; i += 128) sWp[i] = W0p[i];
    for (int i = threadIdx.x; i < 7 * 256; i += 128) {
        sWr[0][i] = W0r0[i]; sWr[1][i] = W0r1[i]; sWr[2][i] = W0r2[i];
    }
    __syncthreads();

    const int lane = threadIdx.x & 31;
    const int s = blockIdx.x * 4 + (threadIdx.x >> 5);

    // pos Jacobian: J_P[o][j] = sum_i G1p[s,o,i] * W0p[j,i]
    float accP[21];
#pragma unroll
    for (int p = 0; p < 21; ++p) accP[p] = 0.0f;
    {
        const float* g = g_G1p + (size_t)s * 1536;
        for (int i = lane; i < 512; i += 32) {
            float g0 = g[i], g1 = g[512 + i], g2 = g[1024 + i];
#pragma unroll
            for (int j = 0; j < 7; ++j) {
                float w = sWp[j * 512 + i];
                accP[j]      += g0 * w;
                accP[7 + j]  += g1 * w;
                accP[14 + j] += g2 * w;
            }
        }
    }
    // heads MLP Jacobians: Jm[t][o][j]
    float accH[42];
#pragma unroll
    for (int p = 0; p < 42; ++p) accH[p] = 0.0f;
#pragma unroll
    for (int t = 0; t < 3; ++t) {
        const float* gr = g_G1r + ((size_t)t * m + s) * 512;
        for (int i = lane; i < 256; i += 32) {
            float g0 = gr[i], g1 = gr[256 + i];
#pragma unroll
            for (int j = 0; j < 7; ++j) {
                float w = sWr[t][j * 256 + i];
                accH[t * 14 + j]     += g0 * w;
                accH[t * 14 + 7 + j] += g1 * w;
            }
        }
    }
#pragma unroll
    for (int p = 0; p < 21; ++p) accP[p] = wred(accP[p]);
#pragma unroll
    for (int p = 0; p < 42; ++p) accH[p] = wred(accH[p]);

    if (lane == 0) {
        float qd[7];
#pragma unroll
        for (int j = 0; j < 7; ++j) qd[j] = x[(size_t)s * 14 + 7 + j];
        float P0 = g_aux[s * 9 + 0], P1 = g_aux[s * 9 + 1], P2 = g_aux[s * 9 + 2];

        float sn[3], cs[3], ang[3];
        float R0[3][7], R1[3][7], R2[3][7];
#pragma unroll
        for (int t = 0; t < 3; ++t) {
            float y0 = g_aux[s * 9 + 3 + 2 * t];
            float y1 = g_aux[s * 9 + 4 + 2 * t];
            float s_ = sinf(y0), cy0 = cosf(y0);
            float c_ = cosf(y1), sy1 = sinf(y1);
            sn[t] = s_; cs[t] = c_;
            ang[t] = atan2f(s_, c_);
            float inv = 1.0f / (s_ * s_ + c_ * c_);
#pragma unroll
            for (int j = 0; j < 7; ++j) {
                float j0 = accH[t * 14 + j], j1 = accH[t * 14 + 7 + j];
                R0[t][j] = cy0 * j0;                               // d sin(y0)/dq
                R1[t][j] = -sy1 * j1;                              // d cos(y1)/dq
                R2[t][j] = inv * (c_ * cy0 * j0 + s_ * sy1 * j1);  // d atan2(s,c)/dq
            }
        }
        float velP[3], v0[3], v1[3];
#pragma unroll
        for (int o = 0; o < 3; ++o) {
            float a = 0.f;
#pragma unroll
            for (int j = 0; j < 7; ++j) a += accP[o * 7 + j] * qd[j];
            velP[o] = a;
        }
#pragma unroll
        for (int t = 0; t < 3; ++t) {
            float a = 0.f, b = 0.f;
#pragma unroll
            for (int j = 0; j < 7; ++j) { a += R0[t][j] * qd[j]; b += R1[t][j] * qd[j]; }
            v0[t] = a; v1[t] = b;
        }

        // out: [P(3), s(3), c(3), velP(3), v0(3), v1(3)]
        float* o1 = out + (size_t)s * 18;
        o1[0] = P0; o1[1] = P1; o1[2] = P2;
#pragma unroll
        for (int t = 0; t < 3; ++t) {
            o1[3 + t] = sn[t]; o1[6 + t] = cs[t];
            o1[12 + t] = v0[t]; o1[15 + t] = v1[t];
        }
#pragma unroll
        for (int o = 0; o < 3; ++o) o1[9 + o] = velP[o];

        // J_tot: rows [JP0,JP1,JP2, R0(r,p,y), R1(r,p,y)]
        float* J = out + (size_t)m * 18 + (size_t)s * 63;
#pragma unroll
        for (int p = 0; p < 21; ++p) J[p] = accP[p];
#pragma unroll
        for (int t = 0; t < 3; ++t)
#pragma unroll
            for (int j = 0; j < 7; ++j) {
                J[(3 + t) * 7 + j] = R0[t][j];
                J[(6 + t) * 7 + j] = R1[t][j];
            }

        // out_angles: [P(3), ang(3)]
        float* oa = out + (size_t)m * 81 + (size_t)s * 6;
        oa[0] = P0; oa[1] = P1; oa[2] = P2;
#pragma unroll
        for (int t = 0; t < 3; ++t) oa[3 + t] = ang[t];

        // J_tot_angles: rows [JP0,JP1,JP2, R2(r,p,y)]
        float* Ja = out + (size_t)m * 87 + (size_t)s * 42;
#pragma unroll
        for (int p = 0; p < 21; ++p) Ja[p] = accP[p];
#pragma unroll
        for (int t = 0; t < 3; ++t)
#pragma unroll
            for (int j = 0; j < 7; ++j) Ja[(3 + t) * 7 + j] = R2[t][j];
    }
}

// ---------------- launch ----------------
extern "C" void kernel_launch(void* const* d_in, const int* in_sizes, int n_in,
                              void* d_out, int out_size) {
    const float* x   = (const float*)d_in[0];
    const float* pW0 = (const float*)d_in[1];
    const float* pb0 = (const float*)d_in[2];
    const float* pW1 = (const float*)d_in[3];
    const float* pb1 = (const float*)d_in[4];
    const float* pW2 = (const float*)d_in[5];
    const float* pb2 = (const float*)d_in[6];
    const float* hW0[3]; const float* hb0[3];
    const float* hW1[3]; const float* hb1[3];
    const float* hW2[3]; const float* hb2[3];
    for (int t = 0; t < 3; ++t) {
        int base = 7 + t * 6;
        hW0[t] = (const float*)d_in[base + 0];
        hb0[t] = (const float*)d_in[base + 1];
        hW1[t] = (const float*)d_in[base + 2];
        hb1[t] = (const float*)d_in[base + 3];
        hW2[t] = (const float*)d_in[base + 4];
        hb2[t] = (const float*)d_in[base + 5];
    }
    const int m = in_sizes[0] / 14;  // 16384
    float* out = (float*)d_out;
    (void)n_in; (void)out_size;

    float *H1p, *H2p, *Ap, *G1p, *H1r, *H2r, *Ar, *G1r, *W1pT, *W1rT;
    cudaGetSymbolAddress((void**)&H1p,  g_H1p);
    cudaGetSymbolAddress((void**)&H2p,  g_H2p);
    cudaGetSymbolAddress((void**)&Ap,   g_Ap);
    cudaGetSymbolAddress((void**)&G1p,  g_G1p);
    cudaGetSymbolAddress((void**)&H1r,  g_H1r);
    cudaGetSymbolAddress((void**)&H2r,  g_H2r);
    cudaGetSymbolAddress((void**)&Ar,   g_Ar);
    cudaGetSymbolAddress((void**)&G1r,  g_G1r);
    cudaGetSymbolAddress((void**)&W1pT, g_W1pT);
    cudaGetSymbolAddress((void**)&W1rT, g_W1rT);

    dim3 tb(32, 8);
    transpose_kernel<<<dim3(16, 16), tb>>>(pW1, W1pT, 512);
    for (int t = 0; t < 3; ++t)
        transpose_kernel<<<dim3(8, 8), tb>>>(hW1[t], W1rT + (size_t)t * 256 * 256, 256);

    // layer-1 forward
    fwd1_kernel<<<dim3(2, m), 256>>>(x, pW0, pb0, H1p, 512);
    for (int t = 0; t < 3; ++t)
        fwd1_kernel<<<dim3(1, m), 256>>>(x, hW0[t], hb0[t], H1r + (size_t)t * m * 256, 256);

    // layer-2 forward GEMMs (sigmoid epilogue)
    sgemm_kernel<1><<<dim3(8, m / 128), 256>>>(512, 512, H1p, pW1, pb1, nullptr, 1, H2p);
    for (int t = 0; t < 3; ++t)
        sgemm_kernel<1><<<dim3(4, m / 128), 256>>>(256, 256, H1r + (size_t)t * m * 256, hW1[t],
                                                   hb1[t], nullptr, 1, H2r + (size_t)t * m * 256);

    // output-layer dots + backward seeds
    seed_kernel<<<m / 4, 128>>>(pW2, pb2, hW2[0], hb2[0], hW2[1], hb2[1], hW2[2], hb2[2], m);

    // backward GEMMs (dsigmoid epilogue): G1 = (A' @ W1^T) .* sigma1'
    sgemm_kernel<2><<<dim3(8, (3 * m) / 128), 256>>>(512, 512, Ap, W1pT, nullptr, H1p, 3, G1p);
    for (int t = 0; t < 3; ++t)
        sgemm_kernel<2><<<dim3(4, (2 * m) / 128), 256>>>(
            256, 256, Ar + (size_t)t * m * 512, W1rT + (size_t)t * 256 * 256, nullptr,
            H1r + (size_t)t * m * 256, 2, G1r + (size_t)t * m * 512);

    // input-side projection + trig chain rule + output assembly
    final_kernel<<<m / 4, 128>>>(x, pW0, hW0[0], hW0[1], hW0[2], out, m);
}